// round 7
// baseline (speedup 1.0000x reference)
#include <cuda_runtime.h>
#include <cuda_bf16.h>
#include <math.h>
#include <stdint.h>

#define DMODEL 512
#define DSTATE 16
#define DCONV  4
#define DINNER 1024
#define BSZ    16
#define SEQL   2048
#define MTOT   (BSZ*SEQL)   /* 32768 rows */

typedef __nv_bfloat16 bf16;

// ---------------- scratch (device globals; allocation-free rule) ----------------
__device__ __align__(16) float g_xp    [(size_t)MTOT*DINNER];   // x_p (pre-conv), fp32
__device__ __align__(16) float g_resact[(size_t)MTOT*DINNER];   // silu(res), fp32 (scan gate)
__device__ __align__(16) float g_xc    [(size_t)MTOT*DINNER];   // silu(conv(x_p)), fp32 (scan u, BC gemm)
__device__ __align__(16) float g_dt    [(size_t)MTOT*DINNER];   // delta, fp32
__device__ __align__(16) float g_bc    [(size_t)MTOT*2*DSTATE]; // [B | C], fp32
__device__ __align__(16) float g_outpre[(size_t)MTOT*DMODEL];   // y@W_out + clip(x)

// bf16 operand copies for tensor-core GEMMs
__device__ __align__(16) bf16 g_xbf   [(size_t)MTOT*DMODEL];    // clip(x)
__device__ __align__(16) bf16 g_xcbf  [(size_t)MTOT*DINNER];    // xc
__device__ __align__(16) bf16 g_ygbf  [(size_t)MTOT*DINNER];    // y * silu(res)
__device__ __align__(16) bf16 g_winbf [(size_t)2*DINNER*DMODEL];
__device__ __align__(16) bf16 g_wdtbf [(size_t)DINNER*DINNER];
__device__ __align__(16) bf16 g_woutbf[(size_t)DMODEL*DINNER];

__device__ __forceinline__ float sigmoid_f(float v) { return 1.0f / (1.0f + __expf(-v)); }
__device__ __forceinline__ float clip10(float v)    { return fminf(fmaxf(v, -10.0f), 10.0f); }

// ---------------- f32x2 packed-FMA helpers (Blackwell) ----------------
__device__ __forceinline__ unsigned long long f2pack(float lo, float hi) {
    unsigned long long r;
    asm("mov.b64 %0, {%1,%2};" : "=l"(r) : "f"(lo), "f"(hi));
    return r;
}
__device__ __forceinline__ void f2unpack(unsigned long long v, float &lo, float &hi) {
    asm("mov.b64 {%0,%1}, %2;" : "=f"(lo), "=f"(hi) : "l"(v));
}
__device__ __forceinline__ void ffma2(unsigned long long &d, unsigned long long a, unsigned long long b) {
    asm("fma.rn.f32x2 %0, %1, %2, %0;" : "+l"(d) : "l"(a), "l"(b));
}

// ---------------- mma helpers ----------------
__device__ __forceinline__ void ldsm_x4(uint32_t &r0, uint32_t &r1, uint32_t &r2, uint32_t &r3,
                                        uint32_t addr) {
    asm volatile("ldmatrix.sync.aligned.m8n8.x4.shared.b16 {%0,%1,%2,%3}, [%4];\n"
                 : "=r"(r0), "=r"(r1), "=r"(r2), "=r"(r3) : "r"(addr));
}
__device__ __forceinline__ void mma_16816(float* c, const uint32_t* a, const uint32_t* b) {
    asm volatile("mma.sync.aligned.m16n8k16.row.col.f32.bf16.bf16.f32 "
                 "{%0,%1,%2,%3}, {%4,%5,%6,%7}, {%8,%9}, {%0,%1,%2,%3};\n"
                 : "+f"(c[0]), "+f"(c[1]), "+f"(c[2]), "+f"(c[3])
                 : "r"(a[0]), "r"(a[1]), "r"(a[2]), "r"(a[3]), "r"(b[0]), "r"(b[1]));
}

// ---------------- conversion pre-passes ----------------
__global__ void prep_x_k(const float* __restrict__ x)
{
    const size_t i4 = (size_t)blockIdx.x * blockDim.x + threadIdx.x;
    if (i4 >= (size_t)MTOT*DMODEL/4) return;
    float4 v = ((const float4*)x)[i4];
    bf16 o[4] = { __float2bfloat16(clip10(v.x)), __float2bfloat16(clip10(v.y)),
                  __float2bfloat16(clip10(v.z)), __float2bfloat16(clip10(v.w)) };
    *(uint2*)(g_xbf + i4*4) = *(const uint2*)o;
}

// SEL: 0 = W_in, 1 = W_dt, 2 = W_out
template<int SEL>
__global__ void cvt_w_k(const float* __restrict__ src, int n4)
{
    const int i4 = blockIdx.x * blockDim.x + threadIdx.x;
    if (i4 >= n4) return;
    float4 v = ((const float4*)src)[i4];
    bf16 o[4] = { __float2bfloat16(v.x), __float2bfloat16(v.y),
                  __float2bfloat16(v.z), __float2bfloat16(v.w) };
    bf16* dst = (SEL == 0) ? g_winbf : (SEL == 1) ? g_wdtbf : g_woutbf;
    *(uint2*)(dst + (size_t)i4*4) = *(const uint2*)o;
}

// ---------------- tensor-core GEMM: C[M,N] = A[M,K] @ W[N,K]^T, bf16 in / f32 acc ----
// CTA tile 128x128, BK=32. 8 warps: warp (wid&3)->m 32-slice, (wid>>2)->n 64-slice.
// Per warp: m-atoms 2 (16), n-atoms 8 (8), k-atoms 2 (16).
// EPI 0: A=g_xbf,  W=g_winbf : n<DINNER -> g_xp = v ; else g_resact = silu(v)
// EPI 1: A=g_xcbf, W=g_wdtbf : g_dt = v + bias[n]
// EPI 3: A=g_ygbf, W=g_woutbf: g_outpre = v + clip10(resadd[m*DMODEL+n])
template<int KD, int EPI>
__global__ void __launch_bounds__(256)
mma_gemm_k(const float* __restrict__ bias, const float* __restrict__ resadd)
{
    __shared__ __align__(16) bf16 sA[128*40];
    __shared__ __align__(16) bf16 sW[128*40];

    const bf16* Asrc = (EPI == 0) ? g_xbf : (EPI == 1) ? g_xcbf : g_ygbf;
    const bf16* Wsrc = (EPI == 0) ? g_winbf : (EPI == 1) ? g_wdtbf : g_woutbf;

    const int tid  = threadIdx.x;
    const int wid  = tid >> 5;
    const int lane = tid & 31;
    const int bm   = blockIdx.y * 128;
    const int bn   = blockIdx.x * 128;
    const int m_w  = (wid & 3) * 32;   // warp m offset in tile
    const int n_w  = (wid >> 2) * 64;  // warp n offset in tile

    // gmem staging indices: 2 segments per thread per operand
    const int srow = tid >> 2;         // 0..63
    const int skse = (tid & 3) * 8;    // k element offset (bf16)

    float acc[2][8][4];
    #pragma unroll
    for (int ma = 0; ma < 2; ma++)
        #pragma unroll
        for (int na = 0; na < 8; na++)
            #pragma unroll
            for (int q = 0; q < 4; q++) acc[ma][na][q] = 0.0f;

    // ldmatrix shared addresses (fixed per lane, advance by ka/ma/np)
    const uint32_t sAbase = (uint32_t)__cvta_generic_to_shared(sA);
    const uint32_t sWbase = (uint32_t)__cvta_generic_to_shared(sW);
    // A: row = m_w + ma*16 + (lane&15); col = ka*16 + (lane>>4)*8
    const int a_r = (lane & 15), a_c = (lane >> 4) * 8;
    // B: row = n_w + np*16 + (lane&7) + ((lane>>4)&1)*8; col = ka*16 + ((lane>>3)&1)*8
    const int b_r = (lane & 7) + ((lane >> 4) & 1) * 8, b_c = ((lane >> 3) & 1) * 8;

    uint4 abuf[2], wbuf[2];
    // prologue: load k-chunk 0
    #pragma unroll
    for (int i = 0; i < 2; i++) {
        const int row = i*64 + srow;
        abuf[i] = *(const uint4*)(Asrc + (size_t)(bm + row)*KD + skse);
        wbuf[i] = *(const uint4*)(Wsrc + (size_t)(bn + row)*KD + skse);
    }
    #pragma unroll
    for (int i = 0; i < 2; i++) {
        const int row = i*64 + srow;
        *(uint4*)(sA + row*40 + skse) = abuf[i];
        *(uint4*)(sW + row*40 + skse) = wbuf[i];
    }
    __syncthreads();

    const int nk = KD / 32;
    for (int kt = 0; kt < nk; kt++) {
        if (kt + 1 < nk) {
            const int k0 = (kt + 1) * 32;
            #pragma unroll
            for (int i = 0; i < 2; i++) {
                const int row = i*64 + srow;
                abuf[i] = *(const uint4*)(Asrc + (size_t)(bm + row)*KD + k0 + skse);
                wbuf[i] = *(const uint4*)(Wsrc + (size_t)(bn + row)*KD + k0 + skse);
            }
        }

        // load all fragments for this 32-k chunk
        uint32_t afr[2][2][4];   // [ma][ka][4]
        uint32_t bfr[2][8][2];   // [ka][na][2]
        #pragma unroll
        for (int ma = 0; ma < 2; ma++)
            #pragma unroll
            for (int ka = 0; ka < 2; ka++) {
                const uint32_t addr = sAbase +
                    (uint32_t)(((m_w + ma*16 + a_r)*40 + ka*16 + a_c) * 2);
                ldsm_x4(afr[ma][ka][0], afr[ma][ka][1], afr[ma][ka][2], afr[ma][ka][3], addr);
            }
        #pragma unroll
        for (int np = 0; np < 4; np++)
            #pragma unroll
            for (int ka = 0; ka < 2; ka++) {
                const uint32_t addr = sWbase +
                    (uint32_t)(((n_w + np*16 + b_r)*40 + ka*16 + b_c) * 2);
                uint32_t r0, r1, r2, r3;
                ldsm_x4(r0, r1, r2, r3, addr);
                bfr[ka][np*2    ][0] = r0; bfr[ka][np*2    ][1] = r1;
                bfr[ka][np*2 + 1][0] = r2; bfr[ka][np*2 + 1][1] = r3;
            }

        #pragma unroll
        for (int ka = 0; ka < 2; ka++)
            #pragma unroll
            for (int ma = 0; ma < 2; ma++)
                #pragma unroll
                for (int na = 0; na < 8; na++)
                    mma_16816(acc[ma][na], afr[ma][ka], bfr[ka][na]);

        __syncthreads();
        if (kt + 1 < nk) {
            #pragma unroll
            for (int i = 0; i < 2; i++) {
                const int row = i*64 + srow;
                *(uint4*)(sA + row*40 + skse) = abuf[i];
                *(uint4*)(sW + row*40 + skse) = wbuf[i];
            }
            __syncthreads();
        }
    }

    // ---------------- epilogue ----------------
    #pragma unroll
    for (int ma = 0; ma < 2; ma++) {
        #pragma unroll
        for (int na = 0; na < 8; na++) {
            const int m0 = bm + m_w + ma*16 + (lane >> 2);
            const int n0 = bn + n_w + na*8 + (lane & 3)*2;
            const float c0 = acc[ma][na][0], c1 = acc[ma][na][1];
            const float c2 = acc[ma][na][2], c3 = acc[ma][na][3];
            if (EPI == 0) {
                if (n0 < DINNER) {
                    *(float2*)(g_xp + (size_t)m0*DINNER + n0)       = make_float2(c0, c1);
                    *(float2*)(g_xp + (size_t)(m0+8)*DINNER + n0)   = make_float2(c2, c3);
                } else {
                    const int nn = n0 - DINNER;
                    *(float2*)(g_resact + (size_t)m0*DINNER + nn) =
                        make_float2(c0 * sigmoid_f(c0), c1 * sigmoid_f(c1));
                    *(float2*)(g_resact + (size_t)(m0+8)*DINNER + nn) =
                        make_float2(c2 * sigmoid_f(c2), c3 * sigmoid_f(c3));
                }
            } else if (EPI == 1) {
                const float b0 = bias[n0], b1 = bias[n0+1];
                *(float2*)(g_dt + (size_t)m0*DINNER + n0)     = make_float2(c0 + b0, c1 + b1);
                *(float2*)(g_dt + (size_t)(m0+8)*DINNER + n0) = make_float2(c2 + b0, c3 + b1);
            } else {
                const float x00 = clip10(resadd[(size_t)m0*DMODEL + n0]);
                const float x01 = clip10(resadd[(size_t)m0*DMODEL + n0 + 1]);
                const float x10 = clip10(resadd[(size_t)(m0+8)*DMODEL + n0]);
                const float x11 = clip10(resadd[(size_t)(m0+8)*DMODEL + n0 + 1]);
                *(float2*)(g_outpre + (size_t)m0*DMODEL + n0)     = make_float2(c0 + x00, c1 + x01);
                *(float2*)(g_outpre + (size_t)(m0+8)*DMODEL + n0) = make_float2(c2 + x10, c3 + x11);
            }
        }
    }
}

// ---------------- fp32 skinny GEMM for [B|C] = xc @ W_x^T (N = 32) ----------------
// BM=128, BN=32, BK=32, TM=8, TN=2, 256 threads.
__global__ void __launch_bounds__(256)
bc_gemm_k(const float* __restrict__ W)
{
    constexpr int BM = 128, BN = 32, BK = 32, TM = 8, TN = 2, THREADS = 256;
    constexpr int AL = (BM*BK)/(THREADS*4);   // 4
    constexpr int WL = (BN*BK)/(THREADS*4);   // 1
    const float* A = g_xc;
    const int K = DINNER;

    __shared__ __align__(16) float As[BK][BM+4];
    __shared__ __align__(16) float Ws[BK][BN+4];

    const int tid = threadIdx.x;
    const int bm  = blockIdx.y * BM;
    const int tx  = tid % (BN/TN);
    const int ty  = tid / (BN/TN);

    unsigned long long acc[TM];
    #pragma unroll
    for (int i = 0; i < TM; i++) acc[i] = 0ULL;

    int arow[AL], acol[AL], wrow[WL], wcol[WL];
    #pragma unroll
    for (int i = 0; i < AL; i++) { int idx = (tid + i*THREADS)*4; arow[i] = idx/BK; acol[i] = idx%BK; }
    #pragma unroll
    for (int i = 0; i < WL; i++) { int idx = (tid + i*THREADS)*4; wrow[i] = idx/BK; wcol[i] = idx%BK; }

    float4 abuf[AL], wbuf[WL];
    #pragma unroll
    for (int i = 0; i < AL; i++)
        abuf[i] = *(const float4*)(A + (size_t)(bm + arow[i])*K + acol[i]);
    #pragma unroll
    for (int i = 0; i < WL; i++)
        wbuf[i] = *(const float4*)(W + (size_t)wrow[i]*K + wcol[i]);
    #pragma unroll
    for (int i = 0; i < AL; i++) {
        As[acol[i]+0][arow[i]] = abuf[i].x; As[acol[i]+1][arow[i]] = abuf[i].y;
        As[acol[i]+2][arow[i]] = abuf[i].z; As[acol[i]+3][arow[i]] = abuf[i].w;
    }
    #pragma unroll
    for (int i = 0; i < WL; i++) {
        Ws[wcol[i]+0][wrow[i]] = wbuf[i].x; Ws[wcol[i]+1][wrow[i]] = wbuf[i].y;
        Ws[wcol[i]+2][wrow[i]] = wbuf[i].z; Ws[wcol[i]+3][wrow[i]] = wbuf[i].w;
    }
    __syncthreads();

    const int nk = K / BK;
    for (int kt = 0; kt < nk; kt++) {
        if (kt + 1 < nk) {
            const int k0 = (kt+1)*BK;
            #pragma unroll
            for (int i = 0; i < AL; i++)
                abuf[i] = *(const float4*)(A + (size_t)(bm + arow[i])*K + k0 + acol[i]);
            #pragma unroll
            for (int i = 0; i < WL; i++)
                wbuf[i] = *(const float4*)(W + (size_t)wrow[i]*K + k0 + wcol[i]);
        }
        #pragma unroll
        for (int kk = 0; kk < BK; kk++) {
            float af[TM], bf0, bf1;
            #pragma unroll
            for (int i = 0; i < TM; i += 4)
                *(float4*)&af[i] = *(const float4*)&As[kk][ty*TM + i];
            float2 bv = *(const float2*)&Ws[kk][tx*TN];
            bf0 = bv.x; bf1 = bv.y;
            unsigned long long bp = f2pack(bf0, bf1);
            #pragma unroll
            for (int i = 0; i < TM; i++) {
                unsigned long long ap = f2pack(af[i], af[i]);
                ffma2(acc[i], ap, bp);
            }
        }
        __syncthreads();
        if (kt + 1 < nk) {
            #pragma unroll
            for (int i = 0; i < AL; i++) {
                As[acol[i]+0][arow[i]] = abuf[i].x; As[acol[i]+1][arow[i]] = abuf[i].y;
                As[acol[i]+2][arow[i]] = abuf[i].z; As[acol[i]+3][arow[i]] = abuf[i].w;
            }
            #pragma unroll
            for (int i = 0; i < WL; i++) {
                Ws[wcol[i]+0][wrow[i]] = wbuf[i].x; Ws[wcol[i]+1][wrow[i]] = wbuf[i].y;
                Ws[wcol[i]+2][wrow[i]] = wbuf[i].z; Ws[wcol[i]+3][wrow[i]] = wbuf[i].w;
            }
            __syncthreads();
        }
    }
    #pragma unroll
    for (int i = 0; i < TM; i++) {
        const int m = bm + ty*TM + i;
        const int n = tx*TN;
        float lo, hi;
        f2unpack(acc[i], lo, hi);
        *(float2*)(g_bc + (size_t)m*(2*DSTATE) + n) = make_float2(lo, hi);
    }
}

// ---------------- causal depthwise conv (k=4) + bias + SiLU ----------------
// writes fp32 g_xc (scan u / BC gemm) and bf16 g_xcbf (dt gemm A)
__global__ void conv_silu_k(const float* __restrict__ cw, const float* __restrict__ cb)
{
    const int idx = blockIdx.x * blockDim.x + threadIdx.x;
    if (idx >= MTOT * (DINNER/4)) return;
    const int d4  = idx & (DINNER/4 - 1);
    const int row = idx >> 8;          // DINNER/4 == 256
    const int s   = row & (SEQL - 1);
    const int di  = d4 * 4;

    float4 w0 = *(const float4*)(cw + (size_t)(di+0)*4);
    float4 w1 = *(const float4*)(cw + (size_t)(di+1)*4);
    float4 w2 = *(const float4*)(cw + (size_t)(di+2)*4);
    float4 w3 = *(const float4*)(cw + (size_t)(di+3)*4);
    const float* wa0 = (const float*)&w0;
    const float* wa1 = (const float*)&w1;
    const float* wa2 = (const float*)&w2;
    const float* wa3 = (const float*)&w3;

    float4 a = *(const float4*)(cb + di);
    #pragma unroll
    for (int t = 0; t < 4; t++) {
        const int sr = s - 3 + t;
        if (sr >= 0) {
            float4 v = *(const float4*)(g_xp + (size_t)(row - 3 + t)*DINNER + di);
            a.x = fmaf(wa0[t], v.x, a.x);
            a.y = fmaf(wa1[t], v.y, a.y);
            a.z = fmaf(wa2[t], v.z, a.z);
            a.w = fmaf(wa3[t], v.w, a.w);
        }
    }
    a.x = a.x * sigmoid_f(a.x);
    a.y = a.y * sigmoid_f(a.y);
    a.z = a.z * sigmoid_f(a.z);
    a.w = a.w * sigmoid_f(a.w);
    *(float4*)(g_xc + (size_t)row*DINNER + di) = a;
    bf16 o[4] = { __float2bfloat16(a.x), __float2bfloat16(a.y),
                  __float2bfloat16(a.z), __float2bfloat16(a.w) };
    *(uint2*)(g_xcbf + (size_t)row*DINNER + di) = *(const uint2*)o;
}

// ---------------- selective scan (+ u*D, * silu(res)) -> bf16 yg ----------------
__global__ void scan_k(const float* __restrict__ A_log, const float* __restrict__ Dp)
{
    __shared__ __align__(16) float sBC[64*32];
    const int lane = threadIdx.x;
    const int b    = blockIdx.x >> 5;          // 512 blocks = 16 b * 32
    const int di0  = (blockIdx.x & 31) << 5;   // 32 channels / block
    const int ch   = di0 + lane;

    float Aj[16];
    #pragma unroll
    for (int j = 0; j < 16; j++) Aj[j] = A_log[j];
    const float Dv = Dp[ch];

    float st[16];
    #pragma unroll
    for (int j = 0; j < 16; j++) st[j] = 0.0f;

    const size_t base = (size_t)b*SEQL*DINNER + ch;
    const float* dtp = g_dt     + base;
    const float* up  = g_xc     + base;
    const float* rp  = g_resact + base;
    bf16*        ygp = g_ygbf   + base;
    const float4* bcb = (const float4*)(g_bc + (size_t)b*SEQL*32);

    float pdt[4], pu[4], pr[4];
    #pragma unroll
    for (int t = 0; t < 4; t++) {
        const size_t off = (size_t)t*DINNER;
        pdt[t] = __ldg(dtp + off); pu[t] = __ldg(up + off); pr[t] = __ldg(rp + off);
    }

    for (int sc = 0; sc < SEQL; sc += 64) {
        __syncwarp();
        #pragma unroll
        for (int i = 0; i < 16; i++)
            ((float4*)sBC)[i*32 + lane] = bcb[(size_t)sc*8 + i*32 + lane];
        __syncwarp();

        for (int s4 = 0; s4 < 64; s4 += 4) {
            float dtv[4], uv[4], rv[4];
            #pragma unroll
            for (int t = 0; t < 4; t++) { dtv[t] = pdt[t]; uv[t] = pu[t]; rv[t] = pr[t]; }
            const int nxt = sc + s4 + 4;
            if (nxt < SEQL) {
                #pragma unroll
                for (int t = 0; t < 4; t++) {
                    const size_t off = (size_t)(nxt + t)*DINNER;
                    pdt[t] = __ldg(dtp + off); pu[t] = __ldg(up + off); pr[t] = __ldg(rp + off);
                }
            }
            #pragma unroll
            for (int t = 0; t < 4; t++) {
                const float d  = dtv[t];
                const float uu = uv[t];
                const float du = d * uu;
                const float* brow = sBC + (s4 + t)*32;
                float Bf[16], Cf[16];
                #pragma unroll
                for (int q = 0; q < 4; q++) {
                    *(float4*)&Bf[q*4] = *(const float4*)(brow + q*4);
                    *(float4*)&Cf[q*4] = *(const float4*)(brow + 16 + q*4);
                }
                float y0 = 0.0f, y1 = 0.0f;
                #pragma unroll
                for (int j = 0; j < 16; j += 2) {
                    float a0 = fminf(fmaxf(d*Aj[j],   -5.0f), 5.0f);
                    float a1 = fminf(fmaxf(d*Aj[j+1], -5.0f), 5.0f);
                    float e0 = __expf(a0);
                    float e1 = __expf(a1);
                    st[j]   = fmaf(e0, st[j],   du*Bf[j]);
                    st[j+1] = fmaf(e1, st[j+1], du*Bf[j+1]);
                    y0 = fmaf(st[j],   Cf[j],   y0);
                    y1 = fmaf(st[j+1], Cf[j+1], y1);
                }
                const float y = y0 + y1 + uu*Dv;
                ygp[(size_t)(sc + s4 + t)*DINNER] = __float2bfloat16(y * rv[t]);
            }
        }
    }
}

// ---------------- LayerNorm over D_MODEL=512, one warp per row ----------------
__global__ void layernorm_k(const float* __restrict__ lng, const float* __restrict__ lnb,
                            float* __restrict__ out)
{
    const int warp = threadIdx.x >> 5;
    const int lane = threadIdx.x & 31;
    const int row  = blockIdx.x * 8 + warp;
    const float* rpt = g_outpre + (size_t)row*DMODEL;

    float4 v[4];
    float s = 0.0f, sq = 0.0f;
    #pragma unroll
    for (int k = 0; k < 4; k++) {
        v[k] = *(const float4*)(rpt + k*128 + lane*4);
        s  += v[k].x + v[k].y + v[k].z + v[k].w;
        sq += v[k].x*v[k].x + v[k].y*v[k].y + v[k].z*v[k].z + v[k].w*v[k].w;
    }
    #pragma unroll
    for (int o = 16; o > 0; o >>= 1) {
        s  += __shfl_xor_sync(0xffffffffu, s,  o);
        sq += __shfl_xor_sync(0xffffffffu, sq, o);
    }
    const float mu  = s  * (1.0f/512.0f);
    const float var = sq * (1.0f/512.0f) - mu*mu;
    const float rs  = rsqrtf(var + 1e-5f);

    float* op = out + (size_t)row*DMODEL;
    #pragma unroll
    for (int k = 0; k < 4; k++) {
        float4 gg = *(const float4*)(lng + k*128 + lane*4);
        float4 bb = *(const float4*)(lnb + k*128 + lane*4);
        float4 r;
        r.x = (v[k].x - mu)*rs*gg.x + bb.x;
        r.y = (v[k].y - mu)*rs*gg.y + bb.y;
        r.z = (v[k].z - mu)*rs*gg.z + bb.z;
        r.w = (v[k].w - mu)*rs*gg.w + bb.w;
        *(float4*)(op + k*128 + lane*4) = r;
    }
}

// ---------------- launch ----------------
extern "C" void kernel_launch(void* const* d_in, const int* in_sizes, int n_in,
                              void* d_out, int out_size)
{
    (void)in_sizes; (void)n_in; (void)out_size;
    const float* x      = (const float*)d_in[0];
    const float* W_in   = (const float*)d_in[1];
    const float* conv_w = (const float*)d_in[2];
    const float* conv_b = (const float*)d_in[3];
    const float* W_x    = (const float*)d_in[4];
    const float* W_dt   = (const float*)d_in[5];
    const float* b_dt   = (const float*)d_in[6];
    const float* A_log  = (const float*)d_in[7];
    const float* Dp     = (const float*)d_in[8];
    const float* W_out  = (const float*)d_in[9];
    const float* ln_g   = (const float*)d_in[10];
    const float* ln_b   = (const float*)d_in[11];
    float* out = (float*)d_out;

    // 0) bf16 conversions (weights + clipped x)
    cvt_w_k<0><<<(2*DINNER*DMODEL/4 + 255)/256, 256>>>(W_in,  2*DINNER*DMODEL/4);
    cvt_w_k<1><<<(DINNER*DINNER/4   + 255)/256, 256>>>(W_dt,  DINNER*DINNER/4);
    cvt_w_k<2><<<(DMODEL*DINNER/4   + 255)/256, 256>>>(W_out, DMODEL*DINNER/4);
    prep_x_k<<<((size_t)MTOT*DMODEL/4 + 255)/256, 256>>>(x);

    // 1) in_proj: clip(x)@W_in^T -> g_xp (fp32), g_resact = silu (fp32)
    mma_gemm_k<DMODEL, 0><<<dim3((2*DINNER)/128, MTOT/128), 256>>>(nullptr, nullptr);
    // 2) depthwise causal conv + bias + silu -> g_xc (fp32) + g_xcbf (bf16)
    conv_silu_k<<<(MTOT*(DINNER/4) + 255)/256, 256>>>(conv_w, conv_b);
    // 3) dt = xc@W_dt^T + b_dt -> g_dt (fp32)
    mma_gemm_k<DINNER, 1><<<dim3(DINNER/128, MTOT/128), 256>>>(b_dt, nullptr);
    // 4) [B|C] = xc@W_x^T (fp32 skinny)
    bc_gemm_k<<<dim3(1, MTOT/128), 256>>>(W_x);
    // 5) selective scan + u*D + gate -> g_ygbf (bf16)
    scan_k<<<BSZ*32, 32>>>(A_log, Dp);
    // 6) out_pre = yg@W_out^T + clip(x) -> g_outpre (fp32)
    mma_gemm_k<DINNER, 3><<<dim3(DMODEL/128, MTOT/128), 256>>>(nullptr, x);
    // 7) LayerNorm -> d_out
    layernorm_k<<<MTOT/8, 256>>>(ln_g, ln_b, out);
}

// round 14
// speedup vs baseline: 1.0586x; 1.0586x over previous
#include <cuda_runtime.h>
#include <cuda_bf16.h>
#include <math.h>
#include <stdint.h>

#define DMODEL 512
#define DSTATE 16
#define DCONV  4
#define DINNER 1024
#define BSZ    16
#define SEQL   2048
#define MTOT   (BSZ*SEQL)   /* 32768 rows */

typedef __nv_bfloat16 bf16;

// ---------------- scratch (device globals; allocation-free rule) ----------------
__device__ __align__(16) float g_xp    [(size_t)MTOT*DINNER];
__device__ __align__(16) float g_resact[(size_t)MTOT*DINNER];
__device__ __align__(16) float g_xc    [(size_t)MTOT*DINNER];
__device__ __align__(16) float g_dt    [(size_t)MTOT*DINNER];
__device__ __align__(16) float g_bc    [(size_t)MTOT*2*DSTATE];
__device__ __align__(16) float g_outpre[(size_t)MTOT*DMODEL];

__device__ __align__(16) bf16 g_xbf   [(size_t)MTOT*DMODEL];
__device__ __align__(16) bf16 g_xcbf  [(size_t)MTOT*DINNER];
__device__ __align__(16) bf16 g_ygbf  [(size_t)MTOT*DINNER];
__device__ __align__(16) bf16 g_winbf [(size_t)2*DINNER*DMODEL];
__device__ __align__(16) bf16 g_wdtbf [(size_t)DINNER*DINNER];
__device__ __align__(16) bf16 g_woutbf[(size_t)DMODEL*DINNER];

__device__ __forceinline__ float sigmoid_f(float v) { return 1.0f / (1.0f + __expf(-v)); }
__device__ __forceinline__ float clip10(float v)    { return fminf(fmaxf(v, -10.0f), 10.0f); }

// ---------------- f32x2 helpers ----------------
__device__ __forceinline__ unsigned long long f2pack(float lo, float hi) {
    unsigned long long r;
    asm("mov.b64 %0, {%1,%2};" : "=l"(r) : "f"(lo), "f"(hi));
    return r;
}
__device__ __forceinline__ void f2unpack(unsigned long long v, float &lo, float &hi) {
    asm("mov.b64 {%0,%1}, %2;" : "=f"(lo), "=f"(hi) : "l"(v));
}
__device__ __forceinline__ void ffma2(unsigned long long &d, unsigned long long a, unsigned long long b) {
    asm("fma.rn.f32x2 %0, %1, %2, %0;" : "+l"(d) : "l"(a), "l"(b));
}

// ---------------- mma / cp.async helpers ----------------
__device__ __forceinline__ uint32_t smem_u32(const void* p) {
    uint32_t a;
    asm("{ .reg .u64 t; cvta.to.shared.u64 t, %1; cvt.u32.u64 %0, t; }" : "=r"(a) : "l"(p));
    return a;
}
__device__ __forceinline__ void ldsm_x4(uint32_t &r0, uint32_t &r1, uint32_t &r2, uint32_t &r3,
                                        uint32_t addr) {
    asm volatile("ldmatrix.sync.aligned.m8n8.x4.shared.b16 {%0,%1,%2,%3}, [%4];\n"
                 : "=r"(r0), "=r"(r1), "=r"(r2), "=r"(r3) : "r"(addr));
}
__device__ __forceinline__ void mma_16816(float* c, const uint32_t* a, const uint32_t* b) {
    asm volatile("mma.sync.aligned.m16n8k16.row.col.f32.bf16.bf16.f32 "
                 "{%0,%1,%2,%3}, {%4,%5,%6,%7}, {%8,%9}, {%0,%1,%2,%3};\n"
                 : "+f"(c[0]), "+f"(c[1]), "+f"(c[2]), "+f"(c[3])
                 : "r"(a[0]), "r"(a[1]), "r"(a[2]), "r"(a[3]), "r"(b[0]), "r"(b[1]));
}
__device__ __forceinline__ void cp_async16(uint32_t dst, const void* src) {
    asm volatile("cp.async.cg.shared.global [%0], [%1], 16;" :: "r"(dst), "l"(src));
}
#define CP_COMMIT() asm volatile("cp.async.commit_group;" ::: "memory")
#define CP_WAIT2()  asm volatile("cp.async.wait_group 2;" ::: "memory")

// ---------------- conversion pre-passes ----------------
__global__ void prep_x_k(const float* __restrict__ x)
{
    const size_t i4 = (size_t)blockIdx.x * blockDim.x + threadIdx.x;
    if (i4 >= (size_t)MTOT*DMODEL/4) return;
    float4 v = ((const float4*)x)[i4];
    bf16 o[4] = { __float2bfloat16(clip10(v.x)), __float2bfloat16(clip10(v.y)),
                  __float2bfloat16(clip10(v.z)), __float2bfloat16(clip10(v.w)) };
    *(uint2*)(g_xbf + i4*4) = *(const uint2*)o;
}

// SEL: 0 = W_in, 1 = W_dt, 2 = W_out
template<int SEL>
__global__ void cvt_w_k(const float* __restrict__ src, int n4)
{
    const int i4 = blockIdx.x * blockDim.x + threadIdx.x;
    if (i4 >= n4) return;
    float4 v = ((const float4*)src)[i4];
    bf16 o[4] = { __float2bfloat16(v.x), __float2bfloat16(v.y),
                  __float2bfloat16(v.z), __float2bfloat16(v.w) };
    bf16* dst = (SEL == 0) ? g_winbf : (SEL == 1) ? g_wdtbf : g_woutbf;
    *(uint2*)(dst + (size_t)i4*4) = *(const uint2*)o;
}

// ---------------- mma.sync GEMM with 4-stage cp.async pipeline ----------------
// C[M,N] = A[M,K] @ W[N,K]^T, bf16 in / f32 acc.
// CTA tile 128x128, BK=32, 8 warps: (wid&3)->m 32-slice, (wid>>2)->n 64-slice.
// Stage layout: per stage 2*128*40 bf16 (A then W), pitch 40 (conflict-free ldmatrix).
// EPI 0: A=g_xbf,  W=g_winbf : n<DINNER -> g_xp ; else g_resact = silu(v)
// EPI 1: A=g_xcbf, W=g_wdtbf : g_dt = v + bias[n]
// EPI 3: A=g_ygbf, W=g_woutbf: g_outpre = v + clip10(resadd[m*DMODEL+n])
#define STG_PITCH 40
#define STG_OP    (128*STG_PITCH*2)      /* bytes per operand per stage: 10240 */
#define STG_BYTES (2*STG_OP)             /* per stage: 20480 */
#define NSTAGE    4
#define GEMM_SMEM (NSTAGE*STG_BYTES)     /* 81920 */

template<int KD, int EPI>
__global__ void __launch_bounds__(256)
mma_gemm_k(const float* __restrict__ bias, const float* __restrict__ resadd)
{
    extern __shared__ char smem[];
    const uint32_t sbase = smem_u32(smem);

    const bf16* Asrc = (EPI == 0) ? g_xbf : (EPI == 1) ? g_xcbf : g_ygbf;
    const bf16* Wsrc = (EPI == 0) ? g_winbf : (EPI == 1) ? g_wdtbf : g_woutbf;

    const int tid  = threadIdx.x;
    const int wid  = tid >> 5;
    const int lane = tid & 31;
    const int bm   = blockIdx.y * 128;
    const int bn   = blockIdx.x * 128;
    const int m_w  = (wid & 3) * 32;
    const int n_w  = (wid >> 2) * 64;

    // staging indices: 2 16B segments per thread per operand
    const int srow = tid >> 2;         // 0..63
    const int skse = (tid & 3) * 8;    // k element offset

    float acc[2][8][4];
    #pragma unroll
    for (int ma = 0; ma < 2; ma++)
        #pragma unroll
        for (int na = 0; na < 8; na++)
            #pragma unroll
            for (int q = 0; q < 4; q++) acc[ma][na][q] = 0.0f;

    // per-lane ldmatrix geometry (identical to validated R7 kernel)
    const int a_r = (lane & 15), a_c = (lane >> 4) * 8;
    const int b_r = (lane & 7) + ((lane >> 4) & 1) * 8, b_c = ((lane >> 3) & 1) * 8;

    const int nk = KD / 32;

    // issue one stage's cp.async loads (4x 16B per thread)
    auto issue_stage = [&](int kt, int st) {
        const int kc = kt * 32;
        const uint32_t so = sbase + st * STG_BYTES;
        #pragma unroll
        for (int i = 0; i < 2; i++) {
            const int row = i * 64 + srow;
            const uint32_t doff = (uint32_t)((row * STG_PITCH + skse) * 2);
            cp_async16(so + doff,            Asrc + (size_t)(bm + row) * KD + kc + skse);
            cp_async16(so + STG_OP + doff,   Wsrc + (size_t)(bn + row) * KD + kc + skse);
        }
    };

    // prologue: stages 0..2
    #pragma unroll
    for (int s = 0; s < NSTAGE - 1; s++) {
        if (s < nk) issue_stage(s, s);
        CP_COMMIT();
    }

    for (int kt = 0; kt < nk; kt++) {
        CP_WAIT2();            // group kt retired (3+kt committed, all but 2 newest done)
        __syncthreads();

        // issue next stage before compute (overlap)
        const int nxt = kt + NSTAGE - 1;
        if (nxt < nk) issue_stage(nxt, nxt & (NSTAGE - 1));
        CP_COMMIT();

        const int st = kt & (NSTAGE - 1);
        const uint32_t sAa = sbase + st * STG_BYTES;
        const uint32_t sWa = sAa + STG_OP;

        uint32_t afr[2][2][4];
        uint32_t bfr[2][8][2];
        #pragma unroll
        for (int ma = 0; ma < 2; ma++)
            #pragma unroll
            for (int ka = 0; ka < 2; ka++) {
                const uint32_t addr = sAa +
                    (uint32_t)(((m_w + ma*16 + a_r)*STG_PITCH + ka*16 + a_c) * 2);
                ldsm_x4(afr[ma][ka][0], afr[ma][ka][1], afr[ma][ka][2], afr[ma][ka][3], addr);
            }
        #pragma unroll
        for (int np = 0; np < 4; np++)
            #pragma unroll
            for (int ka = 0; ka < 2; ka++) {
                const uint32_t addr = sWa +
                    (uint32_t)(((n_w + np*16 + b_r)*STG_PITCH + ka*16 + b_c) * 2);
                uint32_t r0, r1, r2, r3;
                ldsm_x4(r0, r1, r2, r3, addr);
                bfr[ka][np*2    ][0] = r0; bfr[ka][np*2    ][1] = r1;
                bfr[ka][np*2 + 1][0] = r2; bfr[ka][np*2 + 1][1] = r3;
            }

        #pragma unroll
        for (int ka = 0; ka < 2; ka++)
            #pragma unroll
            for (int ma = 0; ma < 2; ma++)
                #pragma unroll
                for (int na = 0; na < 8; na++)
                    mma_16816(acc[ma][na], afr[ma][ka], bfr[ka][na]);
        // no trailing sync needed: next iteration's cp.async targets a stage
        // freed a full iteration ago, and the loop-top __syncthreads orders it.
    }

    // ---------------- epilogue (identical to validated R7 kernel) ----------------
    #pragma unroll
    for (int ma = 0; ma < 2; ma++) {
        #pragma unroll
        for (int na = 0; na < 8; na++) {
            const int m0 = bm + m_w + ma*16 + (lane >> 2);
            const int n0 = bn + n_w + na*8 + (lane & 3)*2;
            const float c0 = acc[ma][na][0], c1 = acc[ma][na][1];
            const float c2 = acc[ma][na][2], c3 = acc[ma][na][3];
            if (EPI == 0) {
                if (n0 < DINNER) {
                    *(float2*)(g_xp + (size_t)m0*DINNER + n0)       = make_float2(c0, c1);
                    *(float2*)(g_xp + (size_t)(m0+8)*DINNER + n0)   = make_float2(c2, c3);
                } else {
                    const int nn = n0 - DINNER;
                    *(float2*)(g_resact + (size_t)m0*DINNER + nn) =
                        make_float2(c0 * sigmoid_f(c0), c1 * sigmoid_f(c1));
                    *(float2*)(g_resact + (size_t)(m0+8)*DINNER + nn) =
                        make_float2(c2 * sigmoid_f(c2), c3 * sigmoid_f(c3));
                }
            } else if (EPI == 1) {
                const float b0 = bias[n0], b1 = bias[n0+1];
                *(float2*)(g_dt + (size_t)m0*DINNER + n0)     = make_float2(c0 + b0, c1 + b1);
                *(float2*)(g_dt + (size_t)(m0+8)*DINNER + n0) = make_float2(c2 + b0, c3 + b1);
            } else {
                const float x00 = clip10(resadd[(size_t)m0*DMODEL + n0]);
                const float x01 = clip10(resadd[(size_t)m0*DMODEL + n0 + 1]);
                const float x10 = clip10(resadd[(size_t)(m0+8)*DMODEL + n0]);
                const float x11 = clip10(resadd[(size_t)(m0+8)*DMODEL + n0 + 1]);
                *(float2*)(g_outpre + (size_t)m0*DMODEL + n0)     = make_float2(c0 + x00, c1 + x01);
                *(float2*)(g_outpre + (size_t)(m0+8)*DMODEL + n0) = make_float2(c2 + x10, c3 + x11);
            }
        }
    }
}

// ---------------- fp32 skinny GEMM for [B|C] = xc @ W_x^T (N = 32) ----------------
__global__ void __launch_bounds__(256)
bc_gemm_k(const float* __restrict__ W)
{
    constexpr int BM = 128, BN = 32, BK = 32, TM = 8, TN = 2, THREADS = 256;
    constexpr int AL = (BM*BK)/(THREADS*4);
    constexpr int WL = (BN*BK)/(THREADS*4);
    const float* A = g_xc;
    const int K = DINNER;

    __shared__ __align__(16) float As[BK][BM+4];
    __shared__ __align__(16) float Ws[BK][BN+4];

    const int tid = threadIdx.x;
    const int bm  = blockIdx.y * BM;
    const int tx  = tid % (BN/TN);
    const int ty  = tid / (BN/TN);

    unsigned long long acc[TM];
    #pragma unroll
    for (int i = 0; i < TM; i++) acc[i] = 0ULL;

    int arow[AL], acol[AL], wrow[WL], wcol[WL];
    #pragma unroll
    for (int i = 0; i < AL; i++) { int idx = (tid + i*THREADS)*4; arow[i] = idx/BK; acol[i] = idx%BK; }
    #pragma unroll
    for (int i = 0; i < WL; i++) { int idx = (tid + i*THREADS)*4; wrow[i] = idx/BK; wcol[i] = idx%BK; }

    float4 abuf[AL], wbuf[WL];
    #pragma unroll
    for (int i = 0; i < AL; i++)
        abuf[i] = *(const float4*)(A + (size_t)(bm + arow[i])*K + acol[i]);
    #pragma unroll
    for (int i = 0; i < WL; i++)
        wbuf[i] = *(const float4*)(W + (size_t)wrow[i]*K + wcol[i]);
    #pragma unroll
    for (int i = 0; i < AL; i++) {
        As[acol[i]+0][arow[i]] = abuf[i].x; As[acol[i]+1][arow[i]] = abuf[i].y;
        As[acol[i]+2][arow[i]] = abuf[i].z; As[acol[i]+3][arow[i]] = abuf[i].w;
    }
    #pragma unroll
    for (int i = 0; i < WL; i++) {
        Ws[wcol[i]+0][wrow[i]] = wbuf[i].x; Ws[wcol[i]+1][wrow[i]] = wbuf[i].y;
        Ws[wcol[i]+2][wrow[i]] = wbuf[i].z; Ws[wcol[i]+3][wrow[i]] = wbuf[i].w;
    }
    __syncthreads();

    const int nk = K / BK;
    for (int kt = 0; kt < nk; kt++) {
        if (kt + 1 < nk) {
            const int k0 = (kt+1)*BK;
            #pragma unroll
            for (int i = 0; i < AL; i++)
                abuf[i] = *(const float4*)(A + (size_t)(bm + arow[i])*K + k0 + acol[i]);
            #pragma unroll
            for (int i = 0; i < WL; i++)
                wbuf[i] = *(const float4*)(W + (size_t)wrow[i]*K + k0 + wcol[i]);
        }
        #pragma unroll
        for (int kk = 0; kk < BK; kk++) {
            float af[TM];
            #pragma unroll
            for (int i = 0; i < TM; i += 4)
                *(float4*)&af[i] = *(const float4*)&As[kk][ty*TM + i];
            float2 bv = *(const float2*)&Ws[kk][tx*TN];
            unsigned long long bp = f2pack(bv.x, bv.y);
            #pragma unroll
            for (int i = 0; i < TM; i++) {
                unsigned long long ap = f2pack(af[i], af[i]);
                ffma2(acc[i], ap, bp);
            }
        }
        __syncthreads();
        if (kt + 1 < nk) {
            #pragma unroll
            for (int i = 0; i < AL; i++) {
                As[acol[i]+0][arow[i]] = abuf[i].x; As[acol[i]+1][arow[i]] = abuf[i].y;
                As[acol[i]+2][arow[i]] = abuf[i].z; As[acol[i]+3][arow[i]] = abuf[i].w;
            }
            #pragma unroll
            for (int i = 0; i < WL; i++) {
                Ws[wcol[i]+0][wrow[i]] = wbuf[i].x; Ws[wcol[i]+1][wrow[i]] = wbuf[i].y;
                Ws[wcol[i]+2][wrow[i]] = wbuf[i].z; Ws[wcol[i]+3][wrow[i]] = wbuf[i].w;
            }
            __syncthreads();
        }
    }
    #pragma unroll
    for (int i = 0; i < TM; i++) {
        const int m = bm + ty*TM + i;
        float lo, hi;
        f2unpack(acc[i], lo, hi);
        *(float2*)(g_bc + (size_t)m*(2*DSTATE) + tx*TN) = make_float2(lo, hi);
    }
}

// ---------------- causal depthwise conv (k=4) + bias + SiLU ----------------
__global__ void conv_silu_k(const float* __restrict__ cw, const float* __restrict__ cb)
{
    const int idx = blockIdx.x * blockDim.x + threadIdx.x;
    if (idx >= MTOT * (DINNER/4)) return;
    const int d4  = idx & (DINNER/4 - 1);
    const int row = idx >> 8;
    const int s   = row & (SEQL - 1);
    const int di  = d4 * 4;

    float4 w0 = *(const float4*)(cw + (size_t)(di+0)*4);
    float4 w1 = *(const float4*)(cw + (size_t)(di+1)*4);
    float4 w2 = *(const float4*)(cw + (size_t)(di+2)*4);
    float4 w3 = *(const float4*)(cw + (size_t)(di+3)*4);
    const float* wa0 = (const float*)&w0;
    const float* wa1 = (const float*)&w1;
    const float* wa2 = (const float*)&w2;
    const float* wa3 = (const float*)&w3;

    float4 a = *(const float4*)(cb + di);
    #pragma unroll
    for (int t = 0; t < 4; t++) {
        const int sr = s - 3 + t;
        if (sr >= 0) {
            float4 v = *(const float4*)(g_xp + (size_t)(row - 3 + t)*DINNER + di);
            a.x = fmaf(wa0[t], v.x, a.x);
            a.y = fmaf(wa1[t], v.y, a.y);
            a.z = fmaf(wa2[t], v.z, a.z);
            a.w = fmaf(wa3[t], v.w, a.w);
        }
    }
    a.x = a.x * sigmoid_f(a.x);
    a.y = a.y * sigmoid_f(a.y);
    a.z = a.z * sigmoid_f(a.z);
    a.w = a.w * sigmoid_f(a.w);
    *(float4*)(g_xc + (size_t)row*DINNER + di) = a;
    bf16 o[4] = { __float2bfloat16(a.x), __float2bfloat16(a.y),
                  __float2bfloat16(a.z), __float2bfloat16(a.w) };
    *(uint2*)(g_xcbf + (size_t)row*DINNER + di) = *(const uint2*)o;
}

// ---------------- selective scan (+ u*D, * silu(res)) -> bf16 yg ----------------
__global__ void scan_k(const float* __restrict__ A_log, const float* __restrict__ Dp)
{
    __shared__ __align__(16) float sBC[64*32];
    const int lane = threadIdx.x;
    const int b    = blockIdx.x >> 5;
    const int di0  = (blockIdx.x & 31) << 5;
    const int ch   = di0 + lane;

    float Aj[16];
    #pragma unroll
    for (int j = 0; j < 16; j++) Aj[j] = A_log[j];
    const float Dv = Dp[ch];

    float st[16];
    #pragma unroll
    for (int j = 0; j < 16; j++) st[j] = 0.0f;

    const size_t base = (size_t)b*SEQL*DINNER + ch;
    const float* dtp = g_dt     + base;
    const float* up  = g_xc     + base;
    const float* rp  = g_resact + base;
    bf16*        ygp = g_ygbf   + base;
    const float4* bcb = (const float4*)(g_bc + (size_t)b*SEQL*32);

    float pdt[4], pu[4], pr[4];
    #pragma unroll
    for (int t = 0; t < 4; t++) {
        const size_t off = (size_t)t*DINNER;
        pdt[t] = __ldg(dtp + off); pu[t] = __ldg(up + off); pr[t] = __ldg(rp + off);
    }

    for (int sc = 0; sc < SEQL; sc += 64) {
        __syncwarp();
        #pragma unroll
        for (int i = 0; i < 16; i++)
            ((float4*)sBC)[i*32 + lane] = bcb[(size_t)sc*8 + i*32 + lane];
        __syncwarp();

        for (int s4 = 0; s4 < 64; s4 += 4) {
            float dtv[4], uv[4], rv[4];
            #pragma unroll
            for (int t = 0; t < 4; t++) { dtv[t] = pdt[t]; uv[t] = pu[t]; rv[t] = pr[t]; }
            const int nxt = sc + s4 + 4;
            if (nxt < SEQL) {
                #pragma unroll
                for (int t = 0; t < 4; t++) {
                    const size_t off = (size_t)(nxt + t)*DINNER;
                    pdt[t] = __ldg(dtp + off); pu[t] = __ldg(up + off); pr[t] = __ldg(rp + off);
                }
            }
            #pragma unroll
            for (int t = 0; t < 4; t++) {
                const float d  = dtv[t];
                const float uu = uv[t];
                const float du = d * uu;
                const float* brow = sBC + (s4 + t)*32;
                float Bf[16], Cf[16];
                #pragma unroll
                for (int q = 0; q < 4; q++) {
                    *(float4*)&Bf[q*4] = *(const float4*)(brow + q*4);
                    *(float4*)&Cf[q*4] = *(const float4*)(brow + 16 + q*4);
                }
                float y0 = 0.0f, y1 = 0.0f;
                #pragma unroll
                for (int j = 0; j < 16; j += 2) {
                    float a0 = fminf(fmaxf(d*Aj[j],   -5.0f), 5.0f);
                    float a1 = fminf(fmaxf(d*Aj[j+1], -5.0f), 5.0f);
                    float e0 = __expf(a0);
                    float e1 = __expf(a1);
                    st[j]   = fmaf(e0, st[j],   du*Bf[j]);
                    st[j+1] = fmaf(e1, st[j+1], du*Bf[j+1]);
                    y0 = fmaf(st[j],   Cf[j],   y0);
                    y1 = fmaf(st[j+1], Cf[j+1], y1);
                }
                const float y = y0 + y1 + uu*Dv;
                ygp[(size_t)(sc + s4 + t)*DINNER] = __float2bfloat16(y * rv[t]);
            }
        }
    }
}

// ---------------- LayerNorm over D_MODEL=512, one warp per row ----------------
__global__ void layernorm_k(const float* __restrict__ lng, const float* __restrict__ lnb,
                            float* __restrict__ out)
{
    const int warp = threadIdx.x >> 5;
    const int lane = threadIdx.x & 31;
    const int row  = blockIdx.x * 8 + warp;
    const float* rpt = g_outpre + (size_t)row*DMODEL;

    float4 v[4];
    float s = 0.0f, sq = 0.0f;
    #pragma unroll
    for (int k = 0; k < 4; k++) {
        v[k] = *(const float4*)(rpt + k*128 + lane*4);
        s  += v[k].x + v[k].y + v[k].z + v[k].w;
        sq += v[k].x*v[k].x + v[k].y*v[k].y + v[k].z*v[k].z + v[k].w*v[k].w;
    }
    #pragma unroll
    for (int o = 16; o > 0; o >>= 1) {
        s  += __shfl_xor_sync(0xffffffffu, s,  o);
        sq += __shfl_xor_sync(0xffffffffu, sq, o);
    }
    const float mu  = s  * (1.0f/512.0f);
    const float var = sq * (1.0f/512.0f) - mu*mu;
    const float rs  = rsqrtf(var + 1e-5f);

    float* op = out + (size_t)row*DMODEL;
    #pragma unroll
    for (int k = 0; k < 4; k++) {
        float4 gg = *(const float4*)(lng + k*128 + lane*4);
        float4 bb = *(const float4*)(lnb + k*128 + lane*4);
        float4 r;
        r.x = (v[k].x - mu)*rs*gg.x + bb.x;
        r.y = (v[k].y - mu)*rs*gg.y + bb.y;
        r.z = (v[k].z - mu)*rs*gg.z + bb.z;
        r.w = (v[k].w - mu)*rs*gg.w + bb.w;
        *(float4*)(op + k*128 + lane*4) = r;
    }
}

// ---------------- launch ----------------
extern "C" void kernel_launch(void* const* d_in, const int* in_sizes, int n_in,
                              void* d_out, int out_size)
{
    (void)in_sizes; (void)n_in; (void)out_size;
    const float* x      = (const float*)d_in[0];
    const float* W_in   = (const float*)d_in[1];
    const float* conv_w = (const float*)d_in[2];
    const float* conv_b = (const float*)d_in[3];
    const float* W_x    = (const float*)d_in[4];
    const float* W_dt   = (const float*)d_in[5];
    const float* b_dt   = (const float*)d_in[6];
    const float* A_log  = (const float*)d_in[7];
    const float* Dp     = (const float*)d_in[8];
    const float* W_out  = (const float*)d_in[9];
    const float* ln_g   = (const float*)d_in[10];
    const float* ln_b   = (const float*)d_in[11];
    float* out = (float*)d_out;

    cudaFuncSetAttribute(mma_gemm_k<DMODEL, 0>, cudaFuncAttributeMaxDynamicSharedMemorySize, GEMM_SMEM);
    cudaFuncSetAttribute(mma_gemm_k<DINNER, 1>, cudaFuncAttributeMaxDynamicSharedMemorySize, GEMM_SMEM);
    cudaFuncSetAttribute(mma_gemm_k<DINNER, 3>, cudaFuncAttributeMaxDynamicSharedMemorySize, GEMM_SMEM);

    // 0) bf16 conversions (weights + clipped x)
    cvt_w_k<0><<<(2*DINNER*DMODEL/4 + 255)/256, 256>>>(W_in,  2*DINNER*DMODEL/4);
    cvt_w_k<1><<<(DINNER*DINNER/4   + 255)/256, 256>>>(W_dt,  DINNER*DINNER/4);
    cvt_w_k<2><<<(DMODEL*DINNER/4   + 255)/256, 256>>>(W_out, DMODEL*DINNER/4);
    prep_x_k<<<((size_t)MTOT*DMODEL/4 + 255)/256, 256>>>(x);

    // 1) in_proj: clip(x)@W_in^T -> g_xp (fp32), g_resact = silu (fp32)
    mma_gemm_k<DMODEL, 0><<<dim3((2*DINNER)/128, MTOT/128), 256, GEMM_SMEM>>>(nullptr, nullptr);
    // 2) depthwise causal conv + bias + silu -> g_xc (fp32) + g_xcbf (bf16)
    conv_silu_k<<<(MTOT*(DINNER/4) + 255)/256, 256>>>(conv_w, conv_b);
    // 3) dt = xc@W_dt^T + b_dt -> g_dt (fp32)
    mma_gemm_k<DINNER, 1><<<dim3(DINNER/128, MTOT/128), 256, GEMM_SMEM>>>(b_dt, nullptr);
    // 4) [B|C] = xc@W_x^T (fp32 skinny)
    bc_gemm_k<<<dim3(1, MTOT/128), 256>>>(W_x);
    // 5) selective scan + u*D + gate -> g_ygbf (bf16)
    scan_k<<<BSZ*32, 32>>>(A_log, Dp);
    // 6) out_pre = yg@W_out^T + clip(x) -> g_outpre (fp32)
    mma_gemm_k<DINNER, 3><<<dim3(DMODEL/128, MTOT/128), 256, GEMM_SMEM>>>(nullptr, x);
    // 7) LayerNorm -> d_out
    layernorm_k<<<MTOT/8, 256>>>(ln_g, ln_b, out);
}